// round 1
// baseline (speedup 1.0000x reference)
#include <cuda_runtime.h>
#include <cstdint>
#include <cstddef>

#define BATCH 32768
#define HDIM  1024

// Scratch ping-pong buffers (device globals: no allocation allowed)
static __device__ float g_bufA[(size_t)BATCH * HDIM];
static __device__ float g_bufB[(size_t)BATCH * HDIM];

// ---------------------------------------------------------------------------
// tf32 helpers
// ---------------------------------------------------------------------------
__device__ __forceinline__ uint32_t f2tf32(float f) {
    uint32_t u;
    asm("cvt.rna.tf32.f32 %0, %1;" : "=r"(u) : "f"(f));
    return u;
}

__device__ __forceinline__ void mma_tf32(float d[4], const uint32_t a[4],
                                         const uint32_t b[2]) {
    asm volatile(
        "mma.sync.aligned.m16n8k8.row.col.f32.tf32.tf32.f32 "
        "{%0,%1,%2,%3}, {%4,%5,%6,%7}, {%8,%9}, {%0,%1,%2,%3};\n"
        : "+f"(d[0]), "+f"(d[1]), "+f"(d[2]), "+f"(d[3])
        : "r"(a[0]), "r"(a[1]), "r"(a[2]), "r"(a[3]),
          "r"(b[0]), "r"(b[1]));
}

// ---------------------------------------------------------------------------
// GEMM: C[M, HDIM] = A[M,K] @ W[HDIM,K]^T + bias      (M=BATCH)
// Block tile 128x128, BK=32, 256 threads (8 warps, each 64x32),
// tf32 mma.sync m16n8k8, fp32 accumulation. Smem pad 36 => conflict-free
// fragment loads (8 rows * stride36 + k covers all 32 banks uniquely).
// ---------------------------------------------------------------------------
__device__ __forceinline__ void load_stage(const float* __restrict__ A,
                                           const float* __restrict__ W,
                                           int K, size_t blockRow, int blockCol,
                                           int lr, int lc, int k0,
                                           float4 stA[4], float4 stB[4]) {
#pragma unroll
    for (int i = 0; i < 4; i++) {
        size_t ar = blockRow + (size_t)(lr + i * 32);
        const float* ap = A + ar * (size_t)K + k0 + lc;
        float4 v = make_float4(0.f, 0.f, 0.f, 0.f);
        if (k0 + lc + 4 <= K) {
            v = *(const float4*)ap;
        } else {
            if (k0 + lc + 0 < K) v.x = ap[0];
            if (k0 + lc + 1 < K) v.y = ap[1];
            if (k0 + lc + 2 < K) v.z = ap[2];
            if (k0 + lc + 3 < K) v.w = ap[3];
        }
        stA[i] = v;

        size_t br = (size_t)(blockCol + lr + i * 32);
        const float* wp = W + br * (size_t)K + k0 + lc;
        float4 w = make_float4(0.f, 0.f, 0.f, 0.f);
        if (k0 + lc + 4 <= K) {
            w = *(const float4*)wp;
        } else {
            if (k0 + lc + 0 < K) w.x = wp[0];
            if (k0 + lc + 1 < K) w.y = wp[1];
            if (k0 + lc + 2 < K) w.z = wp[2];
            if (k0 + lc + 3 < K) w.w = wp[3];
        }
        stB[i] = w;
    }
}

__global__ __launch_bounds__(256, 1)
void gemm_tf32_kernel(const float* __restrict__ A, const float* __restrict__ W,
                      const float* __restrict__ bias, float* __restrict__ C,
                      int K) {
    constexpr int BM = 128, BK = 32, PAD = 36;
    __shared__ float As[BM][PAD];
    __shared__ float Bs[BM][PAD];

    const int tid  = threadIdx.x;
    const int lane = tid & 31;
    const int warp = tid >> 5;
    const int wm   = (warp & 1) * 64;   // warp row offset in tile
    const int wn   = (warp >> 1) * 32;  // warp col offset in tile
    const int g    = lane >> 2;
    const int tq   = lane & 3;

    const size_t blockRow = (size_t)blockIdx.y * BM;
    const int    blockCol = blockIdx.x * 128;

    const int lr = tid >> 3;        // 0..31 (row within tile, stride 32)
    const int lc = (tid & 7) * 4;   // 0,4,...,28

    float acc[4][4][4];
#pragma unroll
    for (int mt = 0; mt < 4; mt++)
#pragma unroll
        for (int nt = 0; nt < 4; nt++)
#pragma unroll
            for (int r = 0; r < 4; r++) acc[mt][nt][r] = 0.f;

    const int nK = (K + BK - 1) / BK;

    float4 stA[4], stB[4];
    load_stage(A, W, K, blockRow, blockCol, lr, lc, 0, stA, stB);
#pragma unroll
    for (int i = 0; i < 4; i++) {
        int r = lr + i * 32;
        As[r][lc + 0] = __uint_as_float(f2tf32(stA[i].x));
        As[r][lc + 1] = __uint_as_float(f2tf32(stA[i].y));
        As[r][lc + 2] = __uint_as_float(f2tf32(stA[i].z));
        As[r][lc + 3] = __uint_as_float(f2tf32(stA[i].w));
        Bs[r][lc + 0] = __uint_as_float(f2tf32(stB[i].x));
        Bs[r][lc + 1] = __uint_as_float(f2tf32(stB[i].y));
        Bs[r][lc + 2] = __uint_as_float(f2tf32(stB[i].z));
        Bs[r][lc + 3] = __uint_as_float(f2tf32(stB[i].w));
    }
    __syncthreads();

    for (int kt = 0; kt < nK; ++kt) {
        if (kt + 1 < nK)
            load_stage(A, W, K, blockRow, blockCol, lr, lc, (kt + 1) * BK, stA, stB);

#pragma unroll
        for (int ks = 0; ks < 4; ks++) {
            const int k0 = ks * 8;
            uint32_t af[4][4];
#pragma unroll
            for (int mt = 0; mt < 4; mt++) {
                int r = wm + mt * 16;
                af[mt][0] = __float_as_uint(As[r + g][k0 + tq]);
                af[mt][1] = __float_as_uint(As[r + g + 8][k0 + tq]);
                af[mt][2] = __float_as_uint(As[r + g][k0 + tq + 4]);
                af[mt][3] = __float_as_uint(As[r + g + 8][k0 + tq + 4]);
            }
            uint32_t bf[4][2];
#pragma unroll
            for (int nt = 0; nt < 4; nt++) {
                int c = wn + nt * 8;
                bf[nt][0] = __float_as_uint(Bs[c + g][k0 + tq]);
                bf[nt][1] = __float_as_uint(Bs[c + g][k0 + tq + 4]);
            }
#pragma unroll
            for (int mt = 0; mt < 4; mt++)
#pragma unroll
                for (int nt = 0; nt < 4; nt++)
                    mma_tf32(acc[mt][nt], af[mt], bf[nt]);
        }
        __syncthreads();
        if (kt + 1 < nK) {
#pragma unroll
            for (int i = 0; i < 4; i++) {
                int r = lr + i * 32;
                As[r][lc + 0] = __uint_as_float(f2tf32(stA[i].x));
                As[r][lc + 1] = __uint_as_float(f2tf32(stA[i].y));
                As[r][lc + 2] = __uint_as_float(f2tf32(stA[i].z));
                As[r][lc + 3] = __uint_as_float(f2tf32(stA[i].w));
                Bs[r][lc + 0] = __uint_as_float(f2tf32(stB[i].x));
                Bs[r][lc + 1] = __uint_as_float(f2tf32(stB[i].y));
                Bs[r][lc + 2] = __uint_as_float(f2tf32(stB[i].z));
                Bs[r][lc + 3] = __uint_as_float(f2tf32(stB[i].w));
            }
            __syncthreads();
        }
    }

    // Epilogue: add bias, write fp32
#pragma unroll
    for (int mt = 0; mt < 4; mt++) {
        size_t row = blockRow + (size_t)(wm + mt * 16 + g);
#pragma unroll
        for (int nt = 0; nt < 4; nt++) {
            int c0 = blockCol + wn + nt * 8 + tq * 2;
            float bv0 = bias[c0], bv1 = bias[c0 + 1];
            float2 v0 = make_float2(acc[mt][nt][0] + bv0, acc[mt][nt][1] + bv1);
            float2 v1 = make_float2(acc[mt][nt][2] + bv0, acc[mt][nt][3] + bv1);
            *(float2*)(C + row * HDIM + c0)       = v0;
            *(float2*)(C + (row + 8) * HDIM + c0) = v1;
        }
    }
}

// ---------------------------------------------------------------------------
// Row-wise mixed activation (in-place), fused with mask * 2.0 for next layer.
// One block (256 threads) per row of 1024 columns.
// ---------------------------------------------------------------------------
__device__ __forceinline__ float block_reduce(float v, bool isMax, float* sh) {
#pragma unroll
    for (int o = 16; o; o >>= 1) {
        float u = __shfl_xor_sync(0xffffffffu, v, o);
        v = isMax ? fmaxf(v, u) : (v + u);
    }
    if ((threadIdx.x & 31) == 0) sh[threadIdx.x >> 5] = v;
    __syncthreads();
    if (threadIdx.x < 32) {
        float r = (threadIdx.x < 8) ? sh[threadIdx.x] : (isMax ? -1e30f : 0.0f);
#pragma unroll
        for (int o = 4; o; o >>= 1) {
            float u = __shfl_xor_sync(0xffffffffu, r, o);
            r = isMax ? fmaxf(r, u) : (r + u);
        }
        if (threadIdx.x == 0) sh[0] = r;
    }
    __syncthreads();
    float res = sh[0];
    __syncthreads();
    return res;
}

__global__ __launch_bounds__(256)
void act_kernel(float* __restrict__ buf, const int* __restrict__ tids,
                const float* __restrict__ mask) {
    __shared__ float sh[8];
    const int t = threadIdx.x;
    const size_t row = blockIdx.x;

    float* p = buf + row * HDIM + t * 4;
    float4 z4  = *(float4*)p;
    int4   tp  = *(const int4*)(tids + t * 4);
    float4 mv  = *(const float4*)(mask + row * HDIM + t * 4);

    float z[4]  = {z4.x, z4.y, z4.z, z4.w};
    int   ty[4] = {tp.x, tp.y, tp.z, tp.w};
    float mk[4] = {mv.x, mv.y, mv.z, mv.w};

    float lm3 = -1e30f, lm4 = -1e30f;
#pragma unroll
    for (int i = 0; i < 4; i++) {
        if (ty[i] == 3) lm3 = fmaxf(lm3, z[i]);
        if (ty[i] == 4) lm4 = fmaxf(lm4, -z[i]);
    }
    float M3 = block_reduce(lm3, true, sh);
    float M4 = block_reduce(lm4, true, sh);

    float ls3 = 0.f, ls4 = 0.f;
#pragma unroll
    for (int i = 0; i < 4; i++) {
        if (ty[i] == 3) ls3 += expf(z[i] - M3);
        if (ty[i] == 4) ls4 += expf(-z[i] - M4);
    }
    float S3 = block_reduce(ls3, false, sh);
    float S4 = block_reduce(ls4, false, sh);
    float inv3 = 1.0f / S3;  // used only when some ty==3 exists (S3>0 then)
    float inv4 = 1.0f / S4;

    float r[4];
#pragma unroll
    for (int i = 0; i < 4; i++) {
        float x = z[i];
        float a;
        int c = ty[i];
        if (c == 0)      a = fmaxf(x, 0.0f);
        else if (c == 1) a = tanhf(x);
        else if (c == 2) a = 1.0f / (1.0f + expf(-x));
        else if (c == 3) a = expf(x - M3) * inv3;
        else if (c == 4) a = expf(-x - M4) * inv4;
        else if (c == 5) a = 0.5f * x * (1.0f + erff(x * 0.70710678118654752f));
        else             a = (x >= 0.0f) ? x : 0.01f * x;
        r[i] = a * mk[i] * 2.0f;
    }
    *(float4*)p = make_float4(r[0], r[1], r[2], r[3]);
}

// ---------------------------------------------------------------------------
// Head: logits = a @ W3^T + b3 (C=10), then log_softmax. One warp per row.
// ---------------------------------------------------------------------------
__global__ __launch_bounds__(256)
void head_kernel(const float* __restrict__ a, const float* __restrict__ W3,
                 const float* __restrict__ b3, float* __restrict__ out) {
    const int warp = threadIdx.x >> 5;
    const int lane = threadIdx.x & 31;
    const size_t row = (size_t)blockIdx.x * 8 + warp;

    const float* ar = a + row * HDIM;
    float acc[10];
#pragma unroll
    for (int j = 0; j < 10; j++) acc[j] = 0.f;

    for (int c = lane * 4; c < HDIM; c += 128) {
        float4 v = *(const float4*)(ar + c);
#pragma unroll
        for (int j = 0; j < 10; j++) {
            float4 w = *(const float4*)(W3 + (size_t)j * HDIM + c);
            acc[j] += v.x * w.x + v.y * w.y + v.z * w.z + v.w * w.w;
        }
    }
#pragma unroll
    for (int j = 0; j < 10; j++)
#pragma unroll
        for (int o = 16; o; o >>= 1)
            acc[j] += __shfl_xor_sync(0xffffffffu, acc[j], o);

    float logits[10];
    float m = -1e30f;
#pragma unroll
    for (int j = 0; j < 10; j++) {
        logits[j] = acc[j] + b3[j];
        m = fmaxf(m, logits[j]);
    }
    float s = 0.f;
#pragma unroll
    for (int j = 0; j < 10; j++) s += expf(logits[j] - m);
    float lse = m + logf(s);
    if (lane < 10) out[row * 10 + lane] = logits[lane] - lse;
}

// ---------------------------------------------------------------------------
// Launch
// ---------------------------------------------------------------------------
extern "C" void kernel_launch(void* const* d_in, const int* in_sizes, int n_in,
                              void* d_out, int out_size) {
    const float* x     = (const float*)d_in[0];
    const float* W0    = (const float*)d_in[1];
    const float* b0    = (const float*)d_in[2];
    const float* W1    = (const float*)d_in[3];
    const float* b1    = (const float*)d_in[4];
    const float* W2    = (const float*)d_in[5];
    const float* b2    = (const float*)d_in[6];
    const float* W3    = (const float*)d_in[7];
    const float* b3    = (const float*)d_in[8];
    const float* mask1 = (const float*)d_in[9];
    const float* mask2 = (const float*)d_in[10];
    const float* mask3 = (const float*)d_in[11];
    const int* type_ids = (const int*)d_in[12];

    float* bufA = nullptr;
    float* bufB = nullptr;
    cudaGetSymbolAddress((void**)&bufA, g_bufA);
    cudaGetSymbolAddress((void**)&bufB, g_bufB);
    float* out = (float*)d_out;

    dim3 gg(HDIM / 128, BATCH / 128);
    gemm_tf32_kernel<<<gg, 256>>>(x, W0, b0, bufA, 784);
    act_kernel<<<BATCH, 256>>>(bufA, type_ids, mask1);
    gemm_tf32_kernel<<<gg, 256>>>(bufA, W1, b1, bufB, HDIM);
    act_kernel<<<BATCH, 256>>>(bufB, type_ids + HDIM, mask2);
    gemm_tf32_kernel<<<gg, 256>>>(bufB, W2, b2, bufA, HDIM);
    act_kernel<<<BATCH, 256>>>(bufA, type_ids + 2 * HDIM, mask3);
    head_kernel<<<BATCH / 8, 256>>>(bufA, W3, b3, out);

    const size_t maskElems = (size_t)BATCH * HDIM;
    float* mdst = out + (size_t)BATCH * 10;
    cudaMemcpyAsync(mdst,                 mask1, maskElems * sizeof(float),
                    cudaMemcpyDeviceToDevice);
    cudaMemcpyAsync(mdst + maskElems,     mask2, maskElems * sizeof(float),
                    cudaMemcpyDeviceToDevice);
    cudaMemcpyAsync(mdst + 2 * maskElems, mask3, maskElems * sizeof(float),
                    cudaMemcpyDeviceToDevice);
}

// round 2
// speedup vs baseline: 1.3511x; 1.3511x over previous
#include <cuda_runtime.h>
#include <cstdint>
#include <cstddef>

#define BATCH 32768
#define HDIM  1024

// Scratch ping-pong buffers (device globals: no allocation allowed)
static __device__ float g_bufA[(size_t)BATCH * HDIM];
static __device__ float g_bufB[(size_t)BATCH * HDIM];

// ---------------------------------------------------------------------------
// tf32 mma (raw fp32 bits in, HW truncates mantissa -> tf32)
// ---------------------------------------------------------------------------
__device__ __forceinline__ void mma_tf32(float d[4], const uint32_t a[4],
                                         const uint32_t b[2]) {
    asm volatile(
        "mma.sync.aligned.m16n8k8.row.col.f32.tf32.tf32.f32 "
        "{%0,%1,%2,%3}, {%4,%5,%6,%7}, {%8,%9}, {%0,%1,%2,%3};\n"
        : "+f"(d[0]), "+f"(d[1]), "+f"(d[2]), "+f"(d[3])
        : "r"(a[0]), "r"(a[1]), "r"(a[2]), "r"(a[3]),
          "r"(b[0]), "r"(b[1]));
}

__device__ __forceinline__ void cp16(uint32_t dst, const float* src, int bytes) {
    asm volatile("cp.async.cg.shared.global [%0], [%1], 16, %2;\n"
                 :: "r"(dst), "l"(src), "r"(bytes));
}
__device__ __forceinline__ void cp_commit() {
    asm volatile("cp.async.commit_group;\n");
}
__device__ __forceinline__ void cp_wait1() {
    asm volatile("cp.async.wait_group 1;\n");
}

// ---------------------------------------------------------------------------
// GEMM: C[M, HDIM] = A[M,K] @ W[HDIM,K]^T + bias      (M=BATCH)
// 128x128x32 tile, 256 threads (8 warps, each 64x32), 3-stage cp.async
// pipeline, tf32 mma.sync, PAD=36 conflict-free smem.
// ---------------------------------------------------------------------------
#define BM 128
#define BK 32
#define PADK 36
#define STAGES 3
#define STAGE_F (BM * PADK)  // floats per matrix per stage

__device__ __forceinline__ void issue_stage(const float* __restrict__ A,
                                            const float* __restrict__ W,
                                            int K, size_t blockRow, int blockCol,
                                            int k0, uint32_t sA, uint32_t sB,
                                            int tid) {
#pragma unroll
    for (int i = 0; i < 4; i++) {
        int chunk = tid + i * 256;       // 0..1023
        int row = chunk >> 3;            // 0..127
        int col = (chunk & 7) * 4;       // 0,4,...,28
        int valid = (k0 + col + 4 <= K) ? 16 : 0;
        const float* pa = A + (blockRow + (size_t)row) * (size_t)K +
                          (valid ? (k0 + col) : 0);
        cp16(sA + (uint32_t)(row * PADK + col) * 4u, pa, valid);
        const float* pb = W + (size_t)(blockCol + row) * (size_t)K +
                          (valid ? (k0 + col) : 0);
        cp16(sB + (uint32_t)(row * PADK + col) * 4u, pb, valid);
    }
}

__global__ __launch_bounds__(256, 2)
void gemm_tf32_kernel(const float* __restrict__ A, const float* __restrict__ W,
                      const float* __restrict__ bias, float* __restrict__ C,
                      int K) {
    extern __shared__ float smem[];  // [STAGES][A:BM*PADK] then [STAGES][B]
    float* smA = smem;
    float* smB = smem + STAGES * STAGE_F;
    uint32_t sbase = (uint32_t)__cvta_generic_to_shared(smem);
    uint32_t sAaddr = sbase;
    uint32_t sBaddr = sbase + STAGES * STAGE_F * 4;

    const int tid  = threadIdx.x;
    const int lane = tid & 31;
    const int warp = tid >> 5;
    const int wm   = (warp & 1) * 64;
    const int wn   = (warp >> 1) * 32;
    const int g    = lane >> 2;
    const int tq   = lane & 3;

    const size_t blockRow = (size_t)blockIdx.y * BM;
    const int    blockCol = blockIdx.x * 128;

    float acc[4][4][4];
#pragma unroll
    for (int mt = 0; mt < 4; mt++)
#pragma unroll
        for (int nt = 0; nt < 4; nt++)
#pragma unroll
            for (int r = 0; r < 4; r++) acc[mt][nt][r] = 0.f;

    const int nK = (K + BK - 1) / BK;

    // Prologue: prefetch STAGES-1 stages
#pragma unroll
    for (int s = 0; s < STAGES - 1; s++) {
        if (s < nK)
            issue_stage(A, W, K, blockRow, blockCol, s * BK,
                        sAaddr + s * STAGE_F * 4, sBaddr + s * STAGE_F * 4, tid);
        cp_commit();
    }

    for (int kt = 0; kt < nK; ++kt) {
        cp_wait1();
        __syncthreads();

        int pf = kt + STAGES - 1;
        if (pf < nK) {
            int st = pf % STAGES;
            issue_stage(A, W, K, blockRow, blockCol, pf * BK,
                        sAaddr + st * STAGE_F * 4, sBaddr + st * STAGE_F * 4, tid);
        }
        cp_commit();

        const float* sA = smA + (kt % STAGES) * STAGE_F;
        const float* sB = smB + (kt % STAGES) * STAGE_F;

#pragma unroll
        for (int ks = 0; ks < 4; ks++) {
            const int k0 = ks * 8;
            uint32_t af[4][4];
#pragma unroll
            for (int mt = 0; mt < 4; mt++) {
                int r = wm + mt * 16;
                af[mt][0] = __float_as_uint(sA[(r + g) * PADK + k0 + tq]);
                af[mt][1] = __float_as_uint(sA[(r + g + 8) * PADK + k0 + tq]);
                af[mt][2] = __float_as_uint(sA[(r + g) * PADK + k0 + tq + 4]);
                af[mt][3] = __float_as_uint(sA[(r + g + 8) * PADK + k0 + tq + 4]);
            }
            uint32_t bf[4][2];
#pragma unroll
            for (int nt = 0; nt < 4; nt++) {
                int c = wn + nt * 8;
                bf[nt][0] = __float_as_uint(sB[(c + g) * PADK + k0 + tq]);
                bf[nt][1] = __float_as_uint(sB[(c + g) * PADK + k0 + tq + 4]);
            }
#pragma unroll
            for (int mt = 0; mt < 4; mt++)
#pragma unroll
                for (int nt = 0; nt < 4; nt++)
                    mma_tf32(acc[mt][nt], af[mt], bf[nt]);
        }
        __syncthreads();
    }

    // Epilogue: add bias, write fp32
#pragma unroll
    for (int mt = 0; mt < 4; mt++) {
        size_t row = blockRow + (size_t)(wm + mt * 16 + g);
#pragma unroll
        for (int nt = 0; nt < 4; nt++) {
            int c0 = blockCol + wn + nt * 8 + tq * 2;
            float bv0 = __ldg(bias + c0), bv1 = __ldg(bias + c0 + 1);
            float2 v0 = make_float2(acc[mt][nt][0] + bv0, acc[mt][nt][1] + bv1);
            float2 v1 = make_float2(acc[mt][nt][2] + bv0, acc[mt][nt][3] + bv1);
            *(float2*)(C + row * HDIM + c0)       = v0;
            *(float2*)(C + (row + 8) * HDIM + c0) = v1;
        }
    }
}

// ---------------------------------------------------------------------------
// Fast activation helpers
// ---------------------------------------------------------------------------
__device__ __forceinline__ float tanh_ap(float x) {
    float r;
    asm("tanh.approx.f32 %0, %1;" : "=f"(r) : "f"(x));
    return r;
}

// ---------------------------------------------------------------------------
// Row-wise mixed activation (in-place), fused with mask * 2.0 for next layer
// AND writes the mask into the output region (replacing D2D copies).
// One block (256 threads) per row of 1024 columns.
// ---------------------------------------------------------------------------
__global__ __launch_bounds__(256)
void act_kernel(float* __restrict__ buf, const int* __restrict__ tids,
                const float* __restrict__ mask, float* __restrict__ mask_out) {
    __shared__ float2 shA[8];
    __shared__ float2 shB[8];
    const int t = threadIdx.x;
    const int lane = t & 31;
    const int wid = t >> 5;
    const size_t row = blockIdx.x;

    float* p = buf + row * HDIM + t * 4;
    float4 z4 = *(float4*)p;
    int4   tp = *(const int4*)(tids + t * 4);
    float4 mv = *(const float4*)(mask + row * HDIM + t * 4);

    // pass mask through to output
    *(float4*)(mask_out + row * HDIM + t * 4) = mv;

    float z[4]  = {z4.x, z4.y, z4.z, z4.w};
    int   ty[4] = {tp.x, tp.y, tp.z, tp.w};
    float mk[4] = {mv.x, mv.y, mv.z, mv.w};

    // --- joint max reduction for types 3 / 4 ---
    float a = -1e30f, b = -1e30f;
#pragma unroll
    for (int i = 0; i < 4; i++) {
        if (ty[i] == 3) a = fmaxf(a, z[i]);
        if (ty[i] == 4) b = fmaxf(b, -z[i]);
    }
#pragma unroll
    for (int o = 16; o; o >>= 1) {
        a = fmaxf(a, __shfl_xor_sync(0xffffffffu, a, o));
        b = fmaxf(b, __shfl_xor_sync(0xffffffffu, b, o));
    }
    if (lane == 0) shA[wid] = make_float2(a, b);
    __syncthreads();
    float2 mres;
    {
        float2 v = shA[t & 7];
        float ra = v.x, rb = v.y;
#pragma unroll
        for (int k = 1; k < 8; k++) {
            float2 u = shA[(t + k) & 7];  // all threads compute; cheap
            ra = fmaxf(ra, u.x);
            rb = fmaxf(rb, u.y);
        }
        mres = make_float2(ra, rb);
    }
    float M3 = mres.x, M4 = mres.y;

    // --- joint sum reduction ---
    float sa = 0.f, sb = 0.f;
#pragma unroll
    for (int i = 0; i < 4; i++) {
        if (ty[i] == 3) sa += __expf(z[i] - M3);
        if (ty[i] == 4) sb += __expf(-z[i] - M4);
    }
#pragma unroll
    for (int o = 16; o; o >>= 1) {
        sa += __shfl_xor_sync(0xffffffffu, sa, o);
        sb += __shfl_xor_sync(0xffffffffu, sb, o);
    }
    if (lane == 0) shB[wid] = make_float2(sa, sb);
    __syncthreads();
    float S3 = 0.f, S4 = 0.f;
#pragma unroll
    for (int k = 0; k < 8; k++) {
        float2 u = shB[k];
        S3 += u.x;
        S4 += u.y;
    }
    float inv3 = __frcp_rn(S3);
    float inv4 = __frcp_rn(S4);

    float r[4];
#pragma unroll
    for (int i = 0; i < 4; i++) {
        float x = z[i];
        float av;
        int c = ty[i];
        if (c == 0)      av = fmaxf(x, 0.0f);
        else if (c == 1) av = tanh_ap(x);
        else if (c == 2) av = 0.5f * tanh_ap(0.5f * x) + 0.5f;
        else if (c == 3) av = __expf(x - M3) * inv3;
        else if (c == 4) av = __expf(-x - M4) * inv4;
        else if (c == 5) av = 0.5f * x * (1.0f + erff(x * 0.70710678118654752f));
        else             av = (x >= 0.0f) ? x : 0.01f * x;
        r[i] = av * mk[i] * 2.0f;
    }
    *(float4*)p = make_float4(r[0], r[1], r[2], r[3]);
}

// ---------------------------------------------------------------------------
// Head: logits = a @ W3^T + b3 (C=10), then log_softmax. One warp per row.
// ---------------------------------------------------------------------------
__global__ __launch_bounds__(256)
void head_kernel(const float* __restrict__ a, const float* __restrict__ W3,
                 const float* __restrict__ b3, float* __restrict__ out) {
    const int warp = threadIdx.x >> 5;
    const int lane = threadIdx.x & 31;
    const size_t row = (size_t)blockIdx.x * 8 + warp;

    const float* ar = a + row * HDIM;
    float acc[10];
#pragma unroll
    for (int j = 0; j < 10; j++) acc[j] = 0.f;

    for (int c = lane * 4; c < HDIM; c += 128) {
        float4 v = *(const float4*)(ar + c);
#pragma unroll
        for (int j = 0; j < 10; j++) {
            float4 w = *(const float4*)(W3 + (size_t)j * HDIM + c);
            acc[j] += v.x * w.x + v.y * w.y + v.z * w.z + v.w * w.w;
        }
    }
#pragma unroll
    for (int j = 0; j < 10; j++)
#pragma unroll
        for (int o = 16; o; o >>= 1)
            acc[j] += __shfl_xor_sync(0xffffffffu, acc[j], o);

    float logits[10];
    float m = -1e30f;
#pragma unroll
    for (int j = 0; j < 10; j++) {
        logits[j] = acc[j] + __ldg(b3 + j);
        m = fmaxf(m, logits[j]);
    }
    float s = 0.f;
#pragma unroll
    for (int j = 0; j < 10; j++) s += __expf(logits[j] - m);
    float lse = m + logf(s);
    if (lane < 10) out[row * 10 + lane] = logits[lane] - lse;
}

// ---------------------------------------------------------------------------
// Launch
// ---------------------------------------------------------------------------
extern "C" void kernel_launch(void* const* d_in, const int* in_sizes, int n_in,
                              void* d_out, int out_size) {
    const float* x     = (const float*)d_in[0];
    const float* W0    = (const float*)d_in[1];
    const float* b0    = (const float*)d_in[2];
    const float* W1    = (const float*)d_in[3];
    const float* b1    = (const float*)d_in[4];
    const float* W2    = (const float*)d_in[5];
    const float* b2    = (const float*)d_in[6];
    const float* W3    = (const float*)d_in[7];
    const float* b3    = (const float*)d_in[8];
    const float* mask1 = (const float*)d_in[9];
    const float* mask2 = (const float*)d_in[10];
    const float* mask3 = (const float*)d_in[11];
    const int* type_ids = (const int*)d_in[12];

    float* bufA = nullptr;
    float* bufB = nullptr;
    cudaGetSymbolAddress((void**)&bufA, g_bufA);
    cudaGetSymbolAddress((void**)&bufB, g_bufB);
    float* out = (float*)d_out;

    const size_t smemBytes = (size_t)STAGES * 2 * STAGE_F * sizeof(float);
    cudaFuncSetAttribute(gemm_tf32_kernel,
                         cudaFuncAttributeMaxDynamicSharedMemorySize,
                         (int)smemBytes);

    const size_t maskElems = (size_t)BATCH * HDIM;
    float* mdst = out + (size_t)BATCH * 10;

    dim3 gg(HDIM / 128, BATCH / 128);
    gemm_tf32_kernel<<<gg, 256, smemBytes>>>(x, W0, b0, bufA, 784);
    act_kernel<<<BATCH, 256>>>(bufA, type_ids, mask1, mdst);
    gemm_tf32_kernel<<<gg, 256, smemBytes>>>(bufA, W1, b1, bufB, HDIM);
    act_kernel<<<BATCH, 256>>>(bufB, type_ids + HDIM, mask2, mdst + maskElems);
    gemm_tf32_kernel<<<gg, 256, smemBytes>>>(bufB, W2, b2, bufA, HDIM);
    act_kernel<<<BATCH, 256>>>(bufA, type_ids + 2 * HDIM, mask3,
                               mdst + 2 * maskElems);
    head_kernel<<<BATCH / 8, 256>>>(bufA, W3, b3, out);
}

// round 5
// speedup vs baseline: 1.7047x; 1.2617x over previous
#include <cuda_runtime.h>
#include <cuda_fp16.h>
#include <cstdint>
#include <cstddef>

#define BATCH 32768
#define HDIM  1024
#define DIN   784

// Scratch buffers (device globals: no allocation allowed)
static __device__ float  g_bufA[(size_t)BATCH * HDIM];           // GEMM f32 out
static __device__ __half g_h[(size_t)BATCH * HDIM];              // act fp16 out
static __device__ __half g_xh[(size_t)BATCH * DIN];              // x fp16
static __device__ __half g_w0h[(size_t)HDIM * DIN];
static __device__ __half g_w1h[(size_t)HDIM * HDIM];
static __device__ __half g_w2h[(size_t)HDIM * HDIM];

// ---------------------------------------------------------------------------
// helpers
// ---------------------------------------------------------------------------
__device__ __forceinline__ uint32_t smem_u32(const void* p) {
    return (uint32_t)__cvta_generic_to_shared(p);
}
#define SWZ128(o) ((o) ^ (((o) >> 3) & 0x70))

__device__ __forceinline__ void cp16(uint32_t dst, const void* src, int bytes) {
    asm volatile("cp.async.cg.shared.global [%0], [%1], 16, %2;\n"
                 :: "r"(dst), "l"(src), "r"(bytes));
}
__device__ __forceinline__ void cp_commit() {
    asm volatile("cp.async.commit_group;\n");
}

__device__ __forceinline__ void ldm_x4(uint32_t (&r)[4], uint32_t addr) {
    asm volatile("ldmatrix.sync.aligned.m8n8.x4.shared.b16 {%0,%1,%2,%3}, [%4];"
                 : "=r"(r[0]), "=r"(r[1]), "=r"(r[2]), "=r"(r[3]) : "r"(addr));
}

__device__ __forceinline__ void mma_fp16(float d[4], const uint32_t a[4],
                                         const uint32_t b[2]) {
    asm volatile(
        "mma.sync.aligned.m16n8k16.row.col.f32.f16.f16.f32 "
        "{%0,%1,%2,%3}, {%4,%5,%6,%7}, {%8,%9}, {%0,%1,%2,%3};\n"
        : "+f"(d[0]), "+f"(d[1]), "+f"(d[2]), "+f"(d[3])
        : "r"(a[0]), "r"(a[1]), "r"(a[2]), "r"(a[3]), "r"(b[0]), "r"(b[1]));
}

// ---------------------------------------------------------------------------
// fp32 -> fp16 convert (grid-stride, float4 granularity)
// ---------------------------------------------------------------------------
__global__ __launch_bounds__(256)
void f2h_kernel(const float* __restrict__ src, __half* __restrict__ dst, int n4) {
    for (int i = blockIdx.x * 256 + threadIdx.x; i < n4; i += gridDim.x * 256) {
        float4 v = *(const float4*)(src + (size_t)i * 4);
        __half2 h0 = __floats2half2_rn(v.x, v.y);
        __half2 h1 = __floats2half2_rn(v.z, v.w);
        uint2 u;
        u.x = *(uint32_t*)&h0;
        u.y = *(uint32_t*)&h1;
        *(uint2*)(dst + (size_t)i * 4) = u;
    }
}

// ---------------------------------------------------------------------------
// GEMM: C[M, HDIM](f32) = A[M,K](f16) @ W[HDIM,K](f16)^T + bias
// CTA tile 128x128, BK=64 halves (128B rows), 3-stage cp.async pipeline,
// SW128 swizzle, ldmatrix fragment loads, m16n8k16 fp16 mma, f32 accum.
// 8 warps: warp tile 64x32.
// ---------------------------------------------------------------------------
#define GSTAGES 3
#define AB_BYTES 16384            // 128 rows * 128B (each of A and B)
#define STG_BYTES (2 * AB_BYTES)

__device__ __forceinline__ void load_chunk(const __half* __restrict__ A,
                                           const __half* __restrict__ W,
                                           int K, size_t blockRow, int blockCol,
                                           int k0, uint32_t stage_base, int tid) {
#pragma unroll
    for (int i = 0; i < 4; i++) {
        int u = tid + i * 256;          // 0..1023
        int row = u >> 3;               // 0..127
        int c16 = u & 7;                // 16B chunk within 128B row
        int col = k0 + c16 * 8;         // halves
        int vb = (col + 8 <= K) ? 16 : 0;
        const __half* src = A + (blockRow + (size_t)row) * (size_t)K +
                            (vb ? col : k0);
        uint32_t off = (uint32_t)(row * 128 + c16 * 16);
        cp16(stage_base + SWZ128(off), src, vb);
    }
#pragma unroll
    for (int i = 0; i < 4; i++) {
        int u = tid + i * 256;
        int row = u >> 3;
        int c16 = u & 7;
        int col = k0 + c16 * 8;
        int vb = (col + 8 <= K) ? 16 : 0;
        const __half* src = W + (size_t)(blockCol + row) * (size_t)K +
                            (vb ? col : k0);
        uint32_t off = (uint32_t)(row * 128 + c16 * 16);
        cp16(stage_base + AB_BYTES + SWZ128(off), src, vb);
    }
}

__global__ __launch_bounds__(256, 2)
void gemm_fp16_kernel(const __half* __restrict__ A, const __half* __restrict__ W,
                      const float* __restrict__ bias, float* __restrict__ C,
                      int K) {
    extern __shared__ char dsm[];
    const uint32_t sbase = (smem_u32(dsm) + 1023u) & ~1023u;

    const int tid  = threadIdx.x;
    const int lane = tid & 31;
    const int warp = tid >> 5;
    const int wm   = (warp & 1) * 64;
    const int wn   = (warp >> 1) * 32;

    const size_t blockRow = (size_t)blockIdx.y * 128;
    const int    blockCol = blockIdx.x * 128;

    float acc[4][4][4];
#pragma unroll
    for (int mt = 0; mt < 4; mt++)
#pragma unroll
        for (int nt = 0; nt < 4; nt++)
#pragma unroll
            for (int r = 0; r < 4; r++) acc[mt][nt][r] = 0.f;

    const int nK = (K + 63) / 64;

    // Prologue: stages 0, 1
#pragma unroll
    for (int s = 0; s < GSTAGES - 1; s++) {
        load_chunk(A, W, K, blockRow, blockCol, s * 64,
                   sbase + (uint32_t)s * STG_BYTES, tid);
        cp_commit();
    }

    // ldmatrix lane-addressing precompute
    const int lrow = lane & 7;
    const int lmat = lane >> 3;              // 0..3
    const int a_radd = (lmat & 1) * 8;       // +8 rows for mats 1,3
    const int a_kadd = (lmat >> 1) * 16;     // +16B (k+8) for mats 2,3
    const int b_nadd = (lmat >> 1) * 8;      // +8 n-rows for mats 2,3
    const int b_kadd = (lmat & 1) * 16;      // +16B for mats 1,3

    for (int kt = 0; kt < nK; ++kt) {
        asm volatile("cp.async.wait_group 1;\n");
        __syncthreads();

        int pf = kt + GSTAGES - 1;
        if (pf < nK)
            load_chunk(A, W, K, blockRow, blockCol, pf * 64,
                       sbase + (uint32_t)(pf % GSTAGES) * STG_BYTES, tid);
        cp_commit();

        const uint32_t aB = sbase + (uint32_t)(kt % GSTAGES) * STG_BYTES;
        const uint32_t bB = aB + AB_BYTES;

#pragma unroll
        for (int kk = 0; kk < 4; kk++) {
            const int kbyte = kk * 32;
            uint32_t af[4][4];
#pragma unroll
            for (int mt = 0; mt < 4; mt++) {
                int row = wm + mt * 16 + a_radd + lrow;
                uint32_t off = (uint32_t)(row * 128 + kbyte + a_kadd);
                ldm_x4(af[mt], aB + SWZ128(off));
            }
            uint32_t bf[2][4];
#pragma unroll
            for (int np = 0; np < 2; np++) {
                int row = wn + np * 16 + b_nadd + lrow;
                uint32_t off = (uint32_t)(row * 128 + kbyte + b_kadd);
                ldm_x4(bf[np], bB + SWZ128(off));
            }
#pragma unroll
            for (int mt = 0; mt < 4; mt++) {
#pragma unroll
                for (int nt = 0; nt < 4; nt++) {
                    uint32_t bb[2] = {bf[nt >> 1][(nt & 1) * 2],
                                      bf[nt >> 1][(nt & 1) * 2 + 1]};
                    mma_fp16(acc[mt][nt], af[mt], bb);
                }
            }
        }
        __syncthreads();
    }

    // Epilogue: bias + f32 store
    const int g  = lane >> 2;
    const int tq = lane & 3;
#pragma unroll
    for (int mt = 0; mt < 4; mt++) {
        size_t row = blockRow + (size_t)(wm + mt * 16 + g);
#pragma unroll
        for (int nt = 0; nt < 4; nt++) {
            int c0 = blockCol + wn + nt * 8 + tq * 2;
            float bv0 = __ldg(bias + c0), bv1 = __ldg(bias + c0 + 1);
            *(float2*)(C + row * HDIM + c0) =
                make_float2(acc[mt][nt][0] + bv0, acc[mt][nt][1] + bv1);
            *(float2*)(C + (row + 8) * HDIM + c0) =
                make_float2(acc[mt][nt][2] + bv0, acc[mt][nt][3] + bv1);
        }
    }
}

// ---------------------------------------------------------------------------
// activation helpers
// ---------------------------------------------------------------------------
__device__ __forceinline__ float tanh_ap(float x) {
    float r;
    asm("tanh.approx.f32 %0, %1;" : "=f"(r) : "f"(x));
    return r;
}

__device__ __forceinline__ float act_eval(float x, int c, float M3, float inv3,
                                          float M4, float inv4) {
    float av;
    if (c == 0)      av = fmaxf(x, 0.0f);
    else if (c == 1) av = tanh_ap(x);
    else if (c == 2) av = 0.5f * tanh_ap(0.5f * x) + 0.5f;
    else if (c == 3) av = __expf(x - M3) * inv3;
    else if (c == 4) av = __expf(-x - M4) * inv4;
    else if (c == 5) av = 0.5f * x * (1.0f + erff(x * 0.70710678118654752f));
    else             av = (x >= 0.0f) ? x : 0.01f * x;
    return av;
}

// ---------------------------------------------------------------------------
// Warp-per-row activation: reads f32 GEMM out, writes fp16 (act*mask*2) for the
// next GEMM + f32 mask passthrough into output region.
// ---------------------------------------------------------------------------
__global__ __launch_bounds__(128)
void act_kernel(const float* __restrict__ buf, const int* __restrict__ tids,
                const float* __restrict__ mask, float* __restrict__ mask_out,
                __half* __restrict__ hout) {
    const int lane = threadIdx.x & 31;
    const size_t row = (size_t)blockIdx.x * 4 + (threadIdx.x >> 5);
    const size_t base = row * HDIM + lane * 4;

    float4 z4[8], m4[8];
    int4 t4[8];
#pragma unroll
    for (int i = 0; i < 8; i++) {
        z4[i] = *(const float4*)(buf + base + i * 128);
        m4[i] = *(const float4*)(mask + base + i * 128);
        t4[i] = *(const int4*)(tids + lane * 4 + i * 128);
        *(float4*)(mask_out + base + i * 128) = m4[i];
    }

    float a = -1e30f, b = -1e30f;
#pragma unroll
    for (int i = 0; i < 8; i++) {
        float zz[4] = {z4[i].x, z4[i].y, z4[i].z, z4[i].w};
        int ty[4] = {t4[i].x, t4[i].y, t4[i].z, t4[i].w};
#pragma unroll
        for (int s = 0; s < 4; s++) {
            if (ty[s] == 3) a = fmaxf(a, zz[s]);
            if (ty[s] == 4) b = fmaxf(b, -zz[s]);
        }
    }
#pragma unroll
    for (int o = 16; o; o >>= 1) {
        a = fmaxf(a, __shfl_xor_sync(0xffffffffu, a, o));
        b = fmaxf(b, __shfl_xor_sync(0xffffffffu, b, o));
    }
    float sa = 0.f, sb = 0.f;
#pragma unroll
    for (int i = 0; i < 8; i++) {
        float zz[4] = {z4[i].x, z4[i].y, z4[i].z, z4[i].w};
        int ty[4] = {t4[i].x, t4[i].y, t4[i].z, t4[i].w};
#pragma unroll
        for (int s = 0; s < 4; s++) {
            if (ty[s] == 3) sa += __expf(zz[s] - a);
            if (ty[s] == 4) sb += __expf(-zz[s] - b);
        }
    }
#pragma unroll
    for (int o = 16; o; o >>= 1) {
        sa += __shfl_xor_sync(0xffffffffu, sa, o);
        sb += __shfl_xor_sync(0xffffffffu, sb, o);
    }
    float inv3 = __frcp_rn(sa), inv4 = __frcp_rn(sb);

#pragma unroll
    for (int i = 0; i < 8; i++) {
        float zz[4] = {z4[i].x, z4[i].y, z4[i].z, z4[i].w};
        int ty[4] = {t4[i].x, t4[i].y, t4[i].z, t4[i].w};
        float mk[4] = {m4[i].x, m4[i].y, m4[i].z, m4[i].w};
        float r0 = act_eval(zz[0], ty[0], a, inv3, b, inv4) * mk[0] * 2.0f;
        float r1 = act_eval(zz[1], ty[1], a, inv3, b, inv4) * mk[1] * 2.0f;
        float r2 = act_eval(zz[2], ty[2], a, inv3, b, inv4) * mk[2] * 2.0f;
        float r3 = act_eval(zz[3], ty[3], a, inv3, b, inv4) * mk[3] * 2.0f;
        __half2 h0 = __floats2half2_rn(r0, r1);
        __half2 h1 = __floats2half2_rn(r2, r3);
        uint2 u;
        u.x = *(uint32_t*)&h0;
        u.y = *(uint32_t*)&h1;
        *(uint2*)(hout + base + i * 128) = u;
    }
}

// ---------------------------------------------------------------------------
// act3 + head fused: activation, mask3*2, dot with W3 (10x1024), log_softmax.
// ---------------------------------------------------------------------------
__global__ __launch_bounds__(128)
void act3_head_kernel(const float* __restrict__ buf, const int* __restrict__ tids,
                      const float* __restrict__ mask, float* __restrict__ mask_out,
                      const float* __restrict__ W3, const float* __restrict__ b3,
                      float* __restrict__ out) {
    const int lane = threadIdx.x & 31;
    const size_t row = (size_t)blockIdx.x * 4 + (threadIdx.x >> 5);
    const size_t base = row * HDIM + lane * 4;

    float4 z4[8], m4[8];
    int4 t4[8];
#pragma unroll
    for (int i = 0; i < 8; i++) {
        z4[i] = *(const float4*)(buf + base + i * 128);
        m4[i] = *(const float4*)(mask + base + i * 128);
        t4[i] = *(const int4*)(tids + lane * 4 + i * 128);
        *(float4*)(mask_out + base + i * 128) = m4[i];
    }

    float a = -1e30f, b = -1e30f;
#pragma unroll
    for (int i = 0; i < 8; i++) {
        float zz[4] = {z4[i].x, z4[i].y, z4[i].z, z4[i].w};
        int ty[4] = {t4[i].x, t4[i].y, t4[i].z, t4[i].w};
#pragma unroll
        for (int s = 0; s < 4; s++) {
            if (ty[s] == 3) a = fmaxf(a, zz[s]);
            if (ty[s] == 4) b = fmaxf(b, -zz[s]);
        }
    }
#pragma unroll
    for (int o = 16; o; o >>= 1) {
        a = fmaxf(a, __shfl_xor_sync(0xffffffffu, a, o));
        b = fmaxf(b, __shfl_xor_sync(0xffffffffu, b, o));
    }
    float sa = 0.f, sb = 0.f;
#pragma unroll
    for (int i = 0; i < 8; i++) {
        float zz[4] = {z4[i].x, z4[i].y, z4[i].z, z4[i].w};
        int ty[4] = {t4[i].x, t4[i].y, t4[i].z, t4[i].w};
#pragma unroll
        for (int s = 0; s < 4; s++) {
            if (ty[s] == 3) sa += __expf(zz[s] - a);
            if (ty[s] == 4) sb += __expf(-zz[s] - b);
        }
    }
#pragma unroll
    for (int o = 16; o; o >>= 1) {
        sa += __shfl_xor_sync(0xffffffffu, sa, o);
        sb += __shfl_xor_sync(0xffffffffu, sb, o);
    }
    float inv3 = __frcp_rn(sa), inv4 = __frcp_rn(sb);

    float acc[10];
#pragma unroll
    for (int j = 0; j < 10; j++) acc[j] = 0.f;

#pragma unroll
    for (int i = 0; i < 8; i++) {
        float zz[4] = {z4[i].x, z4[i].y, z4[i].z, z4[i].w};
        int ty[4] = {t4[i].x, t4[i].y, t4[i].z, t4[i].w};
        float mk[4] = {m4[i].x, m4[i].y, m4[i].z, m4[i].w};
        float r0 = act_eval(zz[0], ty[0], a, inv3, b, inv4) * mk[0] * 2.0f;
        float r1 = act_eval(zz[1], ty[1], a, inv3, b, inv4) * mk[1] * 2.0f;
        float r2 = act_eval(zz[2], ty[2], a, inv3, b, inv4) * mk[2] * 2.0f;
        float r3 = act_eval(zz[3], ty[3], a, inv3, b, inv4) * mk[3] * 2.0f;
        int colbase = lane * 4 + i * 128;
#pragma unroll
        for (int j = 0; j < 10; j++) {
            float4 w = *(const float4*)(W3 + (size_t)j * HDIM + colbase);
            acc[j] += r0 * w.x + r1 * w.y + r2 * w.z + r3 * w.w;
        }
    }
#pragma unroll
    for (int j = 0; j < 10; j++)
#pragma unroll
        for (int o = 16; o; o >>= 1)
            acc[j] += __shfl_xor_sync(0xffffffffu, acc[j], o);

    float logits[10];
    float m = -1e30f;
#pragma unroll
    for (int j = 0; j < 10; j++) {
        logits[j] = acc[j] + __ldg(b3 + j);
        m = fmaxf(m, logits[j]);
    }
    float s = 0.f;
#pragma unroll
    for (int j = 0; j < 10; j++) s += __expf(logits[j] - m);
    float lse = m + logf(s);
    if (lane == 0) {
#pragma unroll
        for (int j = 0; j < 10; j++) out[row * 10 + j] = logits[j] - lse;
    }
}

// ---------------------------------------------------------------------------
// Launch
// ---------------------------------------------------------------------------
extern "C" void kernel_launch(void* const* d_in, const int* in_sizes, int n_in,
                              void* d_out, int out_size) {
    const float* x     = (const float*)d_in[0];
    const float* W0    = (const float*)d_in[1];
    const float* b0    = (const float*)d_in[2];
    const float* W1    = (const float*)d_in[3];
    const float* b1    = (const float*)d_in[4];
    const float* W2    = (const float*)d_in[5];
    const float* b2    = (const float*)d_in[6];
    const float* W3    = (const float*)d_in[7];
    const float* b3    = (const float*)d_in[8];
    const float* mask1 = (const float*)d_in[9];
    const float* mask2 = (const float*)d_in[10];
    const float* mask3 = (const float*)d_in[11];
    const int* type_ids = (const int*)d_in[12];

    float*  bufA = nullptr;
    __half* hbuf = nullptr;
    __half* xh   = nullptr;
    __half* w0h  = nullptr;
    __half* w1h  = nullptr;
    __half* w2h  = nullptr;
    cudaGetSymbolAddress((void**)&bufA, g_bufA);
    cudaGetSymbolAddress((void**)&hbuf, g_h);
    cudaGetSymbolAddress((void**)&xh, g_xh);
    cudaGetSymbolAddress((void**)&w0h, g_w0h);
    cudaGetSymbolAddress((void**)&w1h, g_w1h);
    cudaGetSymbolAddress((void**)&w2h, g_w2h);
    float* out = (float*)d_out;

    const int smemBytes = GSTAGES * STG_BYTES + 1024;
    cudaFuncSetAttribute(gemm_fp16_kernel,
                         cudaFuncAttributeMaxDynamicSharedMemorySize, smemBytes);

    // fp32 -> fp16 conversions
    f2h_kernel<<<1024, 256>>>(x, xh, (int)((size_t)BATCH * DIN / 4));
    f2h_kernel<<<256, 256>>>(W0, w0h, HDIM * DIN / 4);
    f2h_kernel<<<256, 256>>>(W1, w1h, HDIM * HDIM / 4);
    f2h_kernel<<<256, 256>>>(W2, w2h, HDIM * HDIM / 4);

    const size_t maskElems = (size_t)BATCH * HDIM;
    float* mdst = out + (size_t)BATCH * 10;

    dim3 gg(HDIM / 128, BATCH / 128);
    gemm_fp16_kernel<<<gg, 256, smemBytes>>>(xh, w0h, b0, bufA, DIN);
    act_kernel<<<BATCH / 4, 128>>>(bufA, type_ids, mask1, mdst, hbuf);
    gemm_fp16_kernel<<<gg, 256, smemBytes>>>(hbuf, w1h, b1, bufA, HDIM);
    act_kernel<<<BATCH / 4, 128>>>(bufA, type_ids + HDIM, mask2, mdst + maskElems,
                                   hbuf);
    gemm_fp16_kernel<<<gg, 256, smemBytes>>>(hbuf, w2h, b2, bufA, HDIM);
    act3_head_kernel<<<BATCH / 4, 128>>>(bufA, type_ids + 2 * HDIM, mask3,
                                         mdst + 2 * maskElems, W3, b3, out);
}

// round 6
// speedup vs baseline: 1.7190x; 1.0084x over previous
#include <cuda_runtime.h>
#include <cuda_fp16.h>
#include <cstdint>
#include <cstddef>

#define BATCH 32768
#define HDIM  1024
#define DIN   784

// Scratch buffers (device globals: no allocation allowed)
static __device__ float  g_bufA[(size_t)BATCH * HDIM];           // GEMM f32 out
static __device__ __half g_h[(size_t)BATCH * HDIM];              // act fp16 out
static __device__ __half g_xh[(size_t)BATCH * DIN];              // x fp16
static __device__ __half g_w0h[(size_t)HDIM * DIN];
static __device__ __half g_w1h[(size_t)HDIM * HDIM];
static __device__ __half g_w2h[(size_t)HDIM * HDIM];

// ---------------------------------------------------------------------------
// helpers
// ---------------------------------------------------------------------------
__device__ __forceinline__ uint32_t smem_u32(const void* p) {
    return (uint32_t)__cvta_generic_to_shared(p);
}
#define SWZ128(o) ((o) ^ (((o) >> 3) & 0x70))

__device__ __forceinline__ void cp16(uint32_t dst, const void* src, int bytes) {
    asm volatile("cp.async.cg.shared.global [%0], [%1], 16, %2;\n"
                 :: "r"(dst), "l"(src), "r"(bytes));
}
__device__ __forceinline__ void cp_commit() {
    asm volatile("cp.async.commit_group;\n");
}

__device__ __forceinline__ void ldm_x4(uint32_t (&r)[4], uint32_t addr) {
    asm volatile("ldmatrix.sync.aligned.m8n8.x4.shared.b16 {%0,%1,%2,%3}, [%4];"
                 : "=r"(r[0]), "=r"(r[1]), "=r"(r[2]), "=r"(r[3]) : "r"(addr));
}

__device__ __forceinline__ void mma_fp16(float d[4], const uint32_t a[4],
                                         const uint32_t b0, const uint32_t b1) {
    asm volatile(
        "mma.sync.aligned.m16n8k16.row.col.f32.f16.f16.f32 "
        "{%0,%1,%2,%3}, {%4,%5,%6,%7}, {%8,%9}, {%0,%1,%2,%3};\n"
        : "+f"(d[0]), "+f"(d[1]), "+f"(d[2]), "+f"(d[3])
        : "r"(a[0]), "r"(a[1]), "r"(a[2]), "r"(a[3]), "r"(b0), "r"(b1));
}

// ---------------------------------------------------------------------------
// fp32 -> fp16 convert (grid-stride, float4 granularity)
// ---------------------------------------------------------------------------
__global__ __launch_bounds__(256)
void f2h_kernel(const float* __restrict__ src, __half* __restrict__ dst, int n4) {
    for (int i = blockIdx.x * 256 + threadIdx.x; i < n4; i += gridDim.x * 256) {
        float4 v = *(const float4*)(src + (size_t)i * 4);
        __half2 h0 = __floats2half2_rn(v.x, v.y);
        __half2 h1 = __floats2half2_rn(v.z, v.w);
        uint2 u;
        u.x = *(uint32_t*)&h0;
        u.y = *(uint32_t*)&h1;
        *(uint2*)(dst + (size_t)i * 4) = u;
    }
}

// ---------------------------------------------------------------------------
// GEMM: C[M, HDIM](f32) = A[M,K](f16) @ W[HDIM,K](f16)^T + bias
// CTA tile 128(M) x 256(N), BK=64 halves (128B rows), 3-stage cp.async,
// SW128 swizzle, ldmatrix, m16n8k16 fp16 mma, f32 accum.
// 8 warps, warp tile 64x64 (warp grid 2x4).
// ---------------------------------------------------------------------------
#define GSTAGES 3
#define A_BYTES 16384             // 128 rows * 128B
#define B_BYTES 32768             // 256 rows * 128B
#define STG_BYTES (A_BYTES + B_BYTES)

__device__ __forceinline__ void load_chunk(const __half* __restrict__ A,
                                           const __half* __restrict__ W,
                                           int K, size_t blockRow, int blockCol,
                                           int k0, uint32_t stage_base, int tid) {
#pragma unroll
    for (int i = 0; i < 4; i++) {
        int u = tid + i * 256;          // 0..1023
        int row = u >> 3;               // 0..127
        int c16 = u & 7;                // 16B chunk within 128B row
        int col = k0 + c16 * 8;         // halves
        int vb = (col + 8 <= K) ? 16 : 0;
        const __half* src = A + (blockRow + (size_t)row) * (size_t)K +
                            (vb ? col : k0);
        uint32_t off = (uint32_t)(row * 128 + c16 * 16);
        cp16(stage_base + SWZ128(off), src, vb);
    }
#pragma unroll
    for (int i = 0; i < 8; i++) {
        int u = tid + i * 256;          // 0..2047
        int row = u >> 3;               // 0..255
        int c16 = u & 7;
        int col = k0 + c16 * 8;
        int vb = (col + 8 <= K) ? 16 : 0;
        const __half* src = W + (size_t)(blockCol + row) * (size_t)K +
                            (vb ? col : k0);
        uint32_t off = (uint32_t)(row * 128 + c16 * 16);
        cp16(stage_base + A_BYTES + SWZ128(off), src, vb);
    }
}

__global__ __launch_bounds__(256, 1)
void gemm_fp16_kernel(const __half* __restrict__ A, const __half* __restrict__ W,
                      const float* __restrict__ bias, float* __restrict__ C,
                      int K) {
    extern __shared__ char dsm[];
    const uint32_t sbase = (smem_u32(dsm) + 1023u) & ~1023u;

    const int tid  = threadIdx.x;
    const int lane = tid & 31;
    const int warp = tid >> 5;
    const int wm   = (warp & 1) * 64;    // 2 m-tiles of 64
    const int wn   = (warp >> 1) * 64;   // 4 n-tiles of 64

    const size_t blockRow = (size_t)blockIdx.y * 128;
    const int    blockCol = blockIdx.x * 256;

    float acc[4][8][4];
#pragma unroll
    for (int mt = 0; mt < 4; mt++)
#pragma unroll
        for (int nt = 0; nt < 8; nt++)
#pragma unroll
            for (int r = 0; r < 4; r++) acc[mt][nt][r] = 0.f;

    const int nK = (K + 63) / 64;

    // Prologue: stages 0, 1
#pragma unroll
    for (int s = 0; s < GSTAGES - 1; s++) {
        load_chunk(A, W, K, blockRow, blockCol, s * 64,
                   sbase + (uint32_t)s * STG_BYTES, tid);
        cp_commit();
    }

    // ldmatrix lane-addressing precompute
    const int lrow = lane & 7;
    const int lmat = lane >> 3;              // 0..3
    const int a_radd = (lmat & 1) * 8;       // +8 rows for mats 1,3
    const int a_kadd = (lmat >> 1) * 16;     // +16B (k+8) for mats 2,3
    const int b_nadd = (lmat >> 1) * 8;      // +8 n-rows for mats 2,3
    const int b_kadd = (lmat & 1) * 16;      // +16B for mats 1,3

    for (int kt = 0; kt < nK; ++kt) {
        asm volatile("cp.async.wait_group 1;\n");
        __syncthreads();

        int pf = kt + GSTAGES - 1;
        if (pf < nK)
            load_chunk(A, W, K, blockRow, blockCol, pf * 64,
                       sbase + (uint32_t)(pf % GSTAGES) * STG_BYTES, tid);
        cp_commit();

        const uint32_t aB = sbase + (uint32_t)(kt % GSTAGES) * STG_BYTES;
        const uint32_t bB = aB + A_BYTES;

#pragma unroll
        for (int kk = 0; kk < 4; kk++) {
            const int kbyte = kk * 32;
            uint32_t af[4][4];
#pragma unroll
            for (int mt = 0; mt < 4; mt++) {
                int row = wm + mt * 16 + a_radd + lrow;
                uint32_t off = (uint32_t)(row * 128 + kbyte + a_kadd);
                ldm_x4(af[mt], aB + SWZ128(off));
            }
            uint32_t bf[4][4];
#pragma unroll
            for (int np = 0; np < 4; np++) {
                int row = wn + np * 16 + b_nadd + lrow;
                uint32_t off = (uint32_t)(row * 128 + kbyte + b_kadd);
                ldm_x4(bf[np], bB + SWZ128(off));
            }
#pragma unroll
            for (int mt = 0; mt < 4; mt++) {
#pragma unroll
                for (int nt = 0; nt < 8; nt++) {
                    mma_fp16(acc[mt][nt], af[mt],
                             bf[nt >> 1][(nt & 1) * 2],
                             bf[nt >> 1][(nt & 1) * 2 + 1]);
                }
            }
        }
        __syncthreads();
    }

    // Epilogue: bias + f32 store
    const int g  = lane >> 2;
    const int tq = lane & 3;
#pragma unroll
    for (int mt = 0; mt < 4; mt++) {
        size_t row = blockRow + (size_t)(wm + mt * 16 + g);
#pragma unroll
        for (int nt = 0; nt < 8; nt++) {
            int c0 = blockCol + wn + nt * 8 + tq * 2;
            float bv0 = __ldg(bias + c0), bv1 = __ldg(bias + c0 + 1);
            *(float2*)(C + row * HDIM + c0) =
                make_float2(acc[mt][nt][0] + bv0, acc[mt][nt][1] + bv1);
            *(float2*)(C + (row + 8) * HDIM + c0) =
                make_float2(acc[mt][nt][2] + bv0, acc[mt][nt][3] + bv1);
        }
    }
}

// ---------------------------------------------------------------------------
// activation helpers
// ---------------------------------------------------------------------------
__device__ __forceinline__ float tanh_ap(float x) {
    float r;
    asm("tanh.approx.f32 %0, %1;" : "=f"(r) : "f"(x));
    return r;
}

__device__ __forceinline__ float act_eval(float x, int c, float M3, float inv3,
                                          float M4, float inv4) {
    float av;
    if (c == 0)      av = fmaxf(x, 0.0f);
    else if (c == 1) av = tanh_ap(x);
    else if (c == 2) av = 0.5f * tanh_ap(0.5f * x) + 0.5f;
    else if (c == 3) av = __expf(x - M3) * inv3;
    else if (c == 4) av = __expf(-x - M4) * inv4;
    else if (c == 5) av = 0.5f * x * (1.0f + erff(x * 0.70710678118654752f));
    else             av = (x >= 0.0f) ? x : 0.01f * x;
    return av;
}

// ---------------------------------------------------------------------------
// Warp-per-row activation: reads f32 GEMM out, writes fp16 (act*mask*2) for the
// next GEMM + f32 mask passthrough into output region.
// ---------------------------------------------------------------------------
__global__ __launch_bounds__(128)
void act_kernel(const float* __restrict__ buf, const int* __restrict__ tids,
                const float* __restrict__ mask, float* __restrict__ mask_out,
                __half* __restrict__ hout) {
    const int lane = threadIdx.x & 31;
    const size_t row = (size_t)blockIdx.x * 4 + (threadIdx.x >> 5);
    const size_t base = row * HDIM + lane * 4;

    float4 z4[8], m4[8];
    int4 t4[8];
#pragma unroll
    for (int i = 0; i < 8; i++) {
        z4[i] = *(const float4*)(buf + base + i * 128);
        m4[i] = *(const float4*)(mask + base + i * 128);
        t4[i] = *(const int4*)(tids + lane * 4 + i * 128);
        *(float4*)(mask_out + base + i * 128) = m4[i];
    }

    float a = -1e30f, b = -1e30f;
#pragma unroll
    for (int i = 0; i < 8; i++) {
        float zz[4] = {z4[i].x, z4[i].y, z4[i].z, z4[i].w};
        int ty[4] = {t4[i].x, t4[i].y, t4[i].z, t4[i].w};
#pragma unroll
        for (int s = 0; s < 4; s++) {
            if (ty[s] == 3) a = fmaxf(a, zz[s]);
            if (ty[s] == 4) b = fmaxf(b, -zz[s]);
        }
    }
#pragma unroll
    for (int o = 16; o; o >>= 1) {
        a = fmaxf(a, __shfl_xor_sync(0xffffffffu, a, o));
        b = fmaxf(b, __shfl_xor_sync(0xffffffffu, b, o));
    }
    float sa = 0.f, sb = 0.f;
#pragma unroll
    for (int i = 0; i < 8; i++) {
        float zz[4] = {z4[i].x, z4[i].y, z4[i].z, z4[i].w};
        int ty[4] = {t4[i].x, t4[i].y, t4[i].z, t4[i].w};
#pragma unroll
        for (int s = 0; s < 4; s++) {
            if (ty[s] == 3) sa += __expf(zz[s] - a);
            if (ty[s] == 4) sb += __expf(-zz[s] - b);
        }
    }
#pragma unroll
    for (int o = 16; o; o >>= 1) {
        sa += __shfl_xor_sync(0xffffffffu, sa, o);
        sb += __shfl_xor_sync(0xffffffffu, sb, o);
    }
    float inv3 = __frcp_rn(sa), inv4 = __frcp_rn(sb);

#pragma unroll
    for (int i = 0; i < 8; i++) {
        float zz[4] = {z4[i].x, z4[i].y, z4[i].z, z4[i].w};
        int ty[4] = {t4[i].x, t4[i].y, t4[i].z, t4[i].w};
        float mk[4] = {m4[i].x, m4[i].y, m4[i].z, m4[i].w};
        float r0 = act_eval(zz[0], ty[0], a, inv3, b, inv4) * mk[0] * 2.0f;
        float r1 = act_eval(zz[1], ty[1], a, inv3, b, inv4) * mk[1] * 2.0f;
        float r2 = act_eval(zz[2], ty[2], a, inv3, b, inv4) * mk[2] * 2.0f;
        float r3 = act_eval(zz[3], ty[3], a, inv3, b, inv4) * mk[3] * 2.0f;
        __half2 h0 = __floats2half2_rn(r0, r1);
        __half2 h1 = __floats2half2_rn(r2, r3);
        uint2 u;
        u.x = *(uint32_t*)&h0;
        u.y = *(uint32_t*)&h1;
        *(uint2*)(hout + base + i * 128) = u;
    }
}

// ---------------------------------------------------------------------------
// act3 + head fused: activation, mask3*2, dot with W3 (10x1024), log_softmax.
// ---------------------------------------------------------------------------
__global__ __launch_bounds__(128)
void act3_head_kernel(const float* __restrict__ buf, const int* __restrict__ tids,
                      const float* __restrict__ mask, float* __restrict__ mask_out,
                      const float* __restrict__ W3, const float* __restrict__ b3,
                      float* __restrict__ out) {
    const int lane = threadIdx.x & 31;
    const size_t row = (size_t)blockIdx.x * 4 + (threadIdx.x >> 5);
    const size_t base = row * HDIM + lane * 4;

    float4 z4[8], m4[8];
    int4 t4[8];
#pragma unroll
    for (int i = 0; i < 8; i++) {
        z4[i] = *(const float4*)(buf + base + i * 128);
        m4[i] = *(const float4*)(mask + base + i * 128);
        t4[i] = *(const int4*)(tids + lane * 4 + i * 128);
        *(float4*)(mask_out + base + i * 128) = m4[i];
    }

    float a = -1e30f, b = -1e30f;
#pragma unroll
    for (int i = 0; i < 8; i++) {
        float zz[4] = {z4[i].x, z4[i].y, z4[i].z, z4[i].w};
        int ty[4] = {t4[i].x, t4[i].y, t4[i].z, t4[i].w};
#pragma unroll
        for (int s = 0; s < 4; s++) {
            if (ty[s] == 3) a = fmaxf(a, zz[s]);
            if (ty[s] == 4) b = fmaxf(b, -zz[s]);
        }
    }
#pragma unroll
    for (int o = 16; o; o >>= 1) {
        a = fmaxf(a, __shfl_xor_sync(0xffffffffu, a, o));
        b = fmaxf(b, __shfl_xor_sync(0xffffffffu, b, o));
    }
    float sa = 0.f, sb = 0.f;
#pragma unroll
    for (int i = 0; i < 8; i++) {
        float zz[4] = {z4[i].x, z4[i].y, z4[i].z, z4[i].w};
        int ty[4] = {t4[i].x, t4[i].y, t4[i].z, t4[i].w};
#pragma unroll
        for (int s = 0; s < 4; s++) {
            if (ty[s] == 3) sa += __expf(zz[s] - a);
            if (ty[s] == 4) sb += __expf(-zz[s] - b);
        }
    }
#pragma unroll
    for (int o = 16; o; o >>= 1) {
        sa += __shfl_xor_sync(0xffffffffu, sa, o);
        sb += __shfl_xor_sync(0xffffffffu, sb, o);
    }
    float inv3 = __frcp_rn(sa), inv4 = __frcp_rn(sb);

    float acc[10];
#pragma unroll
    for (int j = 0; j < 10; j++) acc[j] = 0.f;

#pragma unroll
    for (int i = 0; i < 8; i++) {
        float zz[4] = {z4[i].x, z4[i].y, z4[i].z, z4[i].w};
        int ty[4] = {t4[i].x, t4[i].y, t4[i].z, t4[i].w};
        float mk[4] = {m4[i].x, m4[i].y, m4[i].z, m4[i].w};
        float r0 = act_eval(zz[0], ty[0], a, inv3, b, inv4) * mk[0] * 2.0f;
        float r1 = act_eval(zz[1], ty[1], a, inv3, b, inv4) * mk[1] * 2.0f;
        float r2 = act_eval(zz[2], ty[2], a, inv3, b, inv4) * mk[2] * 2.0f;
        float r3 = act_eval(zz[3], ty[3], a, inv3, b, inv4) * mk[3] * 2.0f;
        int colbase = lane * 4 + i * 128;
#pragma unroll
        for (int j = 0; j < 10; j++) {
            float4 w = *(const float4*)(W3 + (size_t)j * HDIM + colbase);
            acc[j] += r0 * w.x + r1 * w.y + r2 * w.z + r3 * w.w;
        }
    }
#pragma unroll
    for (int j = 0; j < 10; j++)
#pragma unroll
        for (int o = 16; o; o >>= 1)
            acc[j] += __shfl_xor_sync(0xffffffffu, acc[j], o);

    float logits[10];
    float m = -1e30f;
#pragma unroll
    for (int j = 0; j < 10; j++) {
        logits[j] = acc[j] + __ldg(b3 + j);
        m = fmaxf(m, logits[j]);
    }
    float s = 0.f;
#pragma unroll
    for (int j = 0; j < 10; j++) s += __expf(logits[j] - m);
    float lse = m + logf(s);
    if (lane == 0) {
#pragma unroll
        for (int j = 0; j < 10; j++) out[row * 10 + j] = logits[j] - lse;
    }
}

// ---------------------------------------------------------------------------
// Launch
// ---------------------------------------------------------------------------
extern "C" void kernel_launch(void* const* d_in, const int* in_sizes, int n_in,
                              void* d_out, int out_size) {
    const float* x     = (const float*)d_in[0];
    const float* W0    = (const float*)d_in[1];
    const float* b0    = (const float*)d_in[2];
    const float* W1    = (const float*)d_in[3];
    const float* b1    = (const float*)d_in[4];
    const float* W2    = (const float*)d_in[5];
    const float* b2    = (const float*)d_in[6];
    const float* W3    = (const float*)d_in[7];
    const float* b3    = (const float*)d_in[8];
    const float* mask1 = (const float*)d_in[9];
    const float* mask2 = (const float*)d_in[10];
    const float* mask3 = (const float*)d_in[11];
    const int* type_ids = (const int*)d_in[12];

    float*  bufA = nullptr;
    __half* hbuf = nullptr;
    __half* xh   = nullptr;
    __half* w0h  = nullptr;
    __half* w1h  = nullptr;
    __half* w2h  = nullptr;
    cudaGetSymbolAddress((void**)&bufA, g_bufA);
    cudaGetSymbolAddress((void**)&hbuf, g_h);
    cudaGetSymbolAddress((void**)&xh, g_xh);
    cudaGetSymbolAddress((void**)&w0h, g_w0h);
    cudaGetSymbolAddress((void**)&w1h, g_w1h);
    cudaGetSymbolAddress((void**)&w2h, g_w2h);
    float* out = (float*)d_out;

    const int smemBytes = GSTAGES * STG_BYTES + 1024;
    cudaFuncSetAttribute(gemm_fp16_kernel,
                         cudaFuncAttributeMaxDynamicSharedMemorySize, smemBytes);

    // fp32 -> fp16 conversions
    f2h_kernel<<<1024, 256>>>(x, xh, (int)((size_t)BATCH * DIN / 4));
    f2h_kernel<<<256, 256>>>(W0, w0h, HDIM * DIN / 4);
    f2h_kernel<<<256, 256>>>(W1, w1h, HDIM * HDIM / 4);
    f2h_kernel<<<256, 256>>>(W2, w2h, HDIM * HDIM / 4);

    const size_t maskElems = (size_t)BATCH * HDIM;
    float* mdst = out + (size_t)BATCH * 10;

    dim3 gg(HDIM / 256, BATCH / 128);
    gemm_fp16_kernel<<<gg, 256, smemBytes>>>(xh, w0h, b0, bufA, DIN);
    act_kernel<<<BATCH / 4, 128>>>(bufA, type_ids, mask1, mdst, hbuf);
    gemm_fp16_kernel<<<gg, 256, smemBytes>>>(hbuf, w1h, b1, bufA, HDIM);
    act_kernel<<<BATCH / 4, 128>>>(bufA, type_ids + HDIM, mask2, mdst + maskElems,
                                   hbuf);
    gemm_fp16_kernel<<<gg, 256, smemBytes>>>(hbuf, w2h, b2, bufA, HDIM);
    act3_head_kernel<<<BATCH / 4, 128>>>(bufA, type_ids + 2 * HDIM, mask3,
                                         mdst + 2 * maskElems, W3, b3, out);
}

// round 8
// speedup vs baseline: 1.7525x; 1.0195x over previous
#include <cuda_runtime.h>
#include <cuda_fp16.h>
#include <cstdint>
#include <cstddef>

#define BATCH 32768
#define HDIM  1024
#define DIN   784

// Scratch buffers (device globals: no allocation allowed)
static __device__ __half g_z[(size_t)BATCH * HDIM];              // GEMM fp16 out
static __device__ __half g_h[(size_t)BATCH * HDIM];              // act fp16 out
static __device__ __half g_xh[(size_t)BATCH * DIN];              // x fp16
static __device__ __half g_w0h[(size_t)HDIM * DIN];
static __device__ __half g_w1h[(size_t)HDIM * HDIM];
static __device__ __half g_w2h[(size_t)HDIM * HDIM];

// ---------------------------------------------------------------------------
// helpers
// ---------------------------------------------------------------------------
__device__ __forceinline__ uint32_t smem_u32(const void* p) {
    return (uint32_t)__cvta_generic_to_shared(p);
}
#define SWZ128(o) ((o) ^ (((o) >> 3) & 0x70))

__device__ __forceinline__ void cp16(uint32_t dst, const void* src, int bytes) {
    asm volatile("cp.async.cg.shared.global [%0], [%1], 16, %2;\n"
                 :: "r"(dst), "l"(src), "r"(bytes));
}
__device__ __forceinline__ void cp_commit() {
    asm volatile("cp.async.commit_group;\n");
}

__device__ __forceinline__ void ldm_x4(uint32_t (&r)[4], uint32_t addr) {
    asm volatile("ldmatrix.sync.aligned.m8n8.x4.shared.b16 {%0,%1,%2,%3}, [%4];"
                 : "=r"(r[0]), "=r"(r[1]), "=r"(r[2]), "=r"(r[3]) : "r"(addr));
}

__device__ __forceinline__ void mma_fp16(float d[4], const uint32_t a[4],
                                         const uint32_t b0, const uint32_t b1) {
    asm volatile(
        "mma.sync.aligned.m16n8k16.row.col.f32.f16.f16.f32 "
        "{%0,%1,%2,%3}, {%4,%5,%6,%7}, {%8,%9}, {%0,%1,%2,%3};\n"
        : "+f"(d[0]), "+f"(d[1]), "+f"(d[2]), "+f"(d[3])
        : "r"(a[0]), "r"(a[1]), "r"(a[2]), "r"(a[3]), "r"(b0), "r"(b1));
}

// ---------------------------------------------------------------------------
// fp32 -> fp16 convert (grid-stride, float4 granularity)
// ---------------------------------------------------------------------------
__global__ __launch_bounds__(256)
void f2h_kernel(const float* __restrict__ src, __half* __restrict__ dst, int n4) {
    for (int i = blockIdx.x * 256 + threadIdx.x; i < n4; i += gridDim.x * 256) {
        float4 v = *(const float4*)(src + (size_t)i * 4);
        __half2 h0 = __floats2half2_rn(v.x, v.y);
        __half2 h1 = __floats2half2_rn(v.z, v.w);
        uint2 u;
        u.x = *(uint32_t*)&h0;
        u.y = *(uint32_t*)&h1;
        *(uint2*)(dst + (size_t)i * 4) = u;
    }
}

// ---------------------------------------------------------------------------
// GEMM: C[M, HDIM](fp16) = A[M,K](f16) @ W[HDIM,K](f16)^T + bias
// CTA 128x128, BK=64 halves, 3-stage cp.async, SW128, ldmatrix, m16n8k16,
// f32 accum. 8 warps, warp tile 64x32. Single barrier per k-iter +
// kk-level fragment double buffering.
// ---------------------------------------------------------------------------
#define GSTAGES 3
#define AB_BYTES 16384            // 128 rows * 128B
#define STG_BYTES (2 * AB_BYTES)

__device__ __forceinline__ void load_chunk(const __half* __restrict__ A,
                                           const __half* __restrict__ W,
                                           int K, size_t blockRow, int blockCol,
                                           int k0, uint32_t stage_base, int tid) {
#pragma unroll
    for (int i = 0; i < 4; i++) {
        int u = tid + i * 256;          // 0..1023
        int row = u >> 3;               // 0..127
        int c16 = u & 7;
        int col = k0 + c16 * 8;
        int vb = (col + 8 <= K) ? 16 : 0;
        const __half* src = A + (blockRow + (size_t)row) * (size_t)K +
                            (vb ? col : k0);
        uint32_t off = (uint32_t)(row * 128 + c16 * 16);
        cp16(stage_base + SWZ128(off), src, vb);
    }
#pragma unroll
    for (int i = 0; i < 4; i++) {
        int u = tid + i * 256;
        int row = u >> 3;
        int c16 = u & 7;
        int col = k0 + c16 * 8;
        int vb = (col + 8 <= K) ? 16 : 0;
        const __half* src = W + (size_t)(blockCol + row) * (size_t)K +
                            (vb ? col : k0);
        uint32_t off = (uint32_t)(row * 128 + c16 * 16);
        cp16(stage_base + AB_BYTES + SWZ128(off), src, vb);
    }
}

__global__ __launch_bounds__(256)
void gemm_fp16_kernel(const __half* __restrict__ A, const __half* __restrict__ W,
                      const float* __restrict__ bias, __half* __restrict__ C,
                      int K) {
    extern __shared__ char dsm[];
    const uint32_t sbase = (smem_u32(dsm) + 1023u) & ~1023u;

    const int tid  = threadIdx.x;
    const int lane = tid & 31;
    const int warp = tid >> 5;
    const int wm   = (warp & 1) * 64;
    const int wn   = (warp >> 1) * 32;

    const size_t blockRow = (size_t)blockIdx.y * 128;
    const int    blockCol = blockIdx.x * 128;

    float acc[4][4][4];
#pragma unroll
    for (int mt = 0; mt < 4; mt++)
#pragma unroll
        for (int nt = 0; nt < 4; nt++)
#pragma unroll
            for (int r = 0; r < 4; r++) acc[mt][nt][r] = 0.f;

    const int nK = (K + 63) / 64;

    // ldmatrix lane-addressing precompute
    const int lrow = lane & 7;
    const int lmat = lane >> 3;
    const int a_radd = (lmat & 1) * 8;
    const int a_kadd = (lmat >> 1) * 16;
    const int b_nadd = (lmat >> 1) * 8;
    const int b_kadd = (lmat & 1) * 16;

    // Prologue: stages 0, 1
#pragma unroll
    for (int s = 0; s < GSTAGES - 1; s++) {
        load_chunk(A, W, K, blockRow, blockCol, s * 64,
                   sbase + (uint32_t)s * STG_BYTES, tid);
        cp_commit();
    }
    asm volatile("cp.async.wait_group 1;\n");
    __syncthreads();

    uint32_t af[2][4][4];
    uint32_t bf[2][2][4];

    // helper lambda replacement: load fragments for k-sub kk from stage base
#define LOAD_FRAGS(buf, stageA, stageB, kbyte)                                \
    do {                                                                      \
        _Pragma("unroll")                                                     \
        for (int mt = 0; mt < 4; mt++) {                                      \
            int row = wm + mt * 16 + a_radd + lrow;                           \
            uint32_t off = (uint32_t)(row * 128 + (kbyte) + a_kadd);          \
            ldm_x4(af[buf][mt], (stageA) + SWZ128(off));                      \
        }                                                                     \
        _Pragma("unroll")                                                     \
        for (int np = 0; np < 2; np++) {                                      \
            int row = wn + np * 16 + b_nadd + lrow;                           \
            uint32_t off = (uint32_t)(row * 128 + (kbyte) + b_kadd);          \
            ldm_x4(bf[buf][np], (stageB) + SWZ128(off));                      \
        }                                                                     \
    } while (0)

    {
        uint32_t aB0 = sbase;
        uint32_t bB0 = sbase + AB_BYTES;
        LOAD_FRAGS(0, aB0, bB0, 0);
    }

    for (int kt = 0; kt < nK; ++kt) {
        const uint32_t aB = sbase + (uint32_t)(kt % GSTAGES) * STG_BYTES;
        const uint32_t bB = aB + AB_BYTES;

#pragma unroll
        for (int kk = 0; kk < 4; kk++) {
            const int cur = kk & 1;
            if (kk < 3) LOAD_FRAGS(cur ^ 1, aB, bB, (kk + 1) * 32);
#pragma unroll
            for (int mt = 0; mt < 4; mt++) {
#pragma unroll
                for (int nt = 0; nt < 4; nt++) {
                    mma_fp16(acc[mt][nt], af[cur][mt],
                             bf[cur][nt >> 1][(nt & 1) * 2],
                             bf[cur][nt >> 1][(nt & 1) * 2 + 1]);
                }
            }
        }

        int pf = kt + GSTAGES - 1;
        if (pf < nK)
            load_chunk(A, W, K, blockRow, blockCol, pf * 64,
                       sbase + (uint32_t)(pf % GSTAGES) * STG_BYTES, tid);
        cp_commit();
        asm volatile("cp.async.wait_group 1;\n");
        __syncthreads();

        if (kt + 1 < nK) {
            uint32_t aN = sbase + (uint32_t)((kt + 1) % GSTAGES) * STG_BYTES;
            uint32_t bN = aN + AB_BYTES;
            LOAD_FRAGS(0, aN, bN, 0);
        }
    }

    // Epilogue: bias + fp16 store
    const int g  = lane >> 2;
    const int tq = lane & 3;
#pragma unroll
    for (int mt = 0; mt < 4; mt++) {
        size_t row = blockRow + (size_t)(wm + mt * 16 + g);
#pragma unroll
        for (int nt = 0; nt < 4; nt++) {
            int c0 = blockCol + wn + nt * 8 + tq * 2;
            float bv0 = __ldg(bias + c0), bv1 = __ldg(bias + c0 + 1);
            __half2 v0 = __floats2half2_rn(acc[mt][nt][0] + bv0,
                                           acc[mt][nt][1] + bv1);
            __half2 v1 = __floats2half2_rn(acc[mt][nt][2] + bv0,
                                           acc[mt][nt][3] + bv1);
            *(__half2*)(C + row * HDIM + c0)       = v0;
            *(__half2*)(C + (row + 8) * HDIM + c0) = v1;
        }
    }
}

// ---------------------------------------------------------------------------
// activation helpers
// ---------------------------------------------------------------------------
__device__ __forceinline__ float tanh_ap(float x) {
    float r;
    asm("tanh.approx.f32 %0, %1;" : "=f"(r) : "f"(x));
    return r;
}

__device__ __forceinline__ float act_eval(float x, int c, float M3, float inv3,
                                          float M4, float inv4) {
    float av;
    if (c == 0)      av = fmaxf(x, 0.0f);
    else if (c == 1) av = tanh_ap(x);
    else if (c == 2) av = 0.5f * tanh_ap(0.5f * x) + 0.5f;
    else if (c == 3) av = __expf(x - M3) * inv3;
    else if (c == 4) av = __expf(-x - M4) * inv4;
    else if (c == 5) av = 0.5f * x * (1.0f + erff(x * 0.70710678118654752f));
    else             av = (x >= 0.0f) ? x : 0.01f * x;
    return av;
}

// ---------------------------------------------------------------------------
// Warp-per-row activation: reads fp16 GEMM out, writes fp16 (act*mask*2)
// + f32 mask passthrough into output region.
// ---------------------------------------------------------------------------
__global__ __launch_bounds__(128)
void act_kernel(const __half* __restrict__ zbuf, const int* __restrict__ tids,
                const float* __restrict__ mask, float* __restrict__ mask_out,
                __half* __restrict__ hout) {
    const int lane = threadIdx.x & 31;
    const size_t row = (size_t)blockIdx.x * 4 + (threadIdx.x >> 5);
    const size_t base = row * HDIM + lane * 4;

    float z[8][4];
    float4 m4[8];
    int4 t4[8];
#pragma unroll
    for (int i = 0; i < 8; i++) {
        uint2 u = *(const uint2*)(zbuf + base + i * 128);
        __half2 h0 = *(__half2*)&u.x;
        __half2 h1 = *(__half2*)&u.y;
        float2 f0 = __half22float2(h0);
        float2 f1 = __half22float2(h1);
        z[i][0] = f0.x; z[i][1] = f0.y; z[i][2] = f1.x; z[i][3] = f1.y;
        m4[i] = *(const float4*)(mask + base + i * 128);
        t4[i] = *(const int4*)(tids + lane * 4 + i * 128);
        *(float4*)(mask_out + base + i * 128) = m4[i];
    }

    float a = -1e30f, b = -1e30f;
#pragma unroll
    for (int i = 0; i < 8; i++) {
        int ty[4] = {t4[i].x, t4[i].y, t4[i].z, t4[i].w};
#pragma unroll
        for (int s = 0; s < 4; s++) {
            if (ty[s] == 3) a = fmaxf(a, z[i][s]);
            if (ty[s] == 4) b = fmaxf(b, -z[i][s]);
        }
    }
#pragma unroll
    for (int o = 16; o; o >>= 1) {
        a = fmaxf(a, __shfl_xor_sync(0xffffffffu, a, o));
        b = fmaxf(b, __shfl_xor_sync(0xffffffffu, b, o));
    }
    float sa = 0.f, sb = 0.f;
#pragma unroll
    for (int i = 0; i < 8; i++) {
        int ty[4] = {t4[i].x, t4[i].y, t4[i].z, t4[i].w};
#pragma unroll
        for (int s = 0; s < 4; s++) {
            if (ty[s] == 3) sa += __expf(z[i][s] - a);
            if (ty[s] == 4) sb += __expf(-z[i][s] - b);
        }
    }
#pragma unroll
    for (int o = 16; o; o >>= 1) {
        sa += __shfl_xor_sync(0xffffffffu, sa, o);
        sb += __shfl_xor_sync(0xffffffffu, sb, o);
    }
    float inv3 = __frcp_rn(sa), inv4 = __frcp_rn(sb);

#pragma unroll
    for (int i = 0; i < 8; i++) {
        int ty[4] = {t4[i].x, t4[i].y, t4[i].z, t4[i].w};
        float mk[4] = {m4[i].x, m4[i].y, m4[i].z, m4[i].w};
        float r0 = act_eval(z[i][0], ty[0], a, inv3, b, inv4) * mk[0] * 2.0f;
        float r1 = act_eval(z[i][1], ty[1], a, inv3, b, inv4) * mk[1] * 2.0f;
        float r2 = act_eval(z[i][2], ty[2], a, inv3, b, inv4) * mk[2] * 2.0f;
        float r3 = act_eval(z[i][3], ty[3], a, inv3, b, inv4) * mk[3] * 2.0f;
        __half2 h0 = __floats2half2_rn(r0, r1);
        __half2 h1 = __floats2half2_rn(r2, r3);
        uint2 u;
        u.x = *(uint32_t*)&h0;
        u.y = *(uint32_t*)&h1;
        *(uint2*)(hout + base + i * 128) = u;
    }
}

// ---------------------------------------------------------------------------
// act3 + head fused: activation, mask3*2, dot with W3 (10x1024), log_softmax.
// ---------------------------------------------------------------------------
__global__ __launch_bounds__(128)
void act3_head_kernel(const __half* __restrict__ zbuf, const int* __restrict__ tids,
                      const float* __restrict__ mask, float* __restrict__ mask_out,
                      const float* __restrict__ W3, const float* __restrict__ b3,
                      float* __restrict__ out) {
    const int lane = threadIdx.x & 31;
    const size_t row = (size_t)blockIdx.x * 4 + (threadIdx.x >> 5);
    const size_t base = row * HDIM + lane * 4;

    float z[8][4];
    float4 m4[8];
    int4 t4[8];
#pragma unroll
    for (int i = 0; i < 8; i++) {
        uint2 u = *(const uint2*)(zbuf + base + i * 128);
        __half2 h0 = *(__half2*)&u.x;
        __half2 h1 = *(__half2*)&u.y;
        float2 f0 = __half22float2(h0);
        float2 f1 = __half22float2(h1);
        z[i][0] = f0.x; z[i][1] = f0.y; z[i][2] = f1.x; z[i][3] = f1.y;
        m4[i] = *(const float4*)(mask + base + i * 128);
        t4[i] = *(const int4*)(tids + lane * 4 + i * 128);
        *(float4*)(mask_out + base + i * 128) = m4[i];
    }

    float a = -1e30f, b = -1e30f;
#pragma unroll
    for (int i = 0; i < 8; i++) {
        int ty[4] = {t4[i].x, t4[i].y, t4[i].z, t4[i].w};
#pragma unroll
        for (int s = 0; s < 4; s++) {
            if (ty[s] == 3) a = fmaxf(a, z[i][s]);
            if (ty[s] == 4) b = fmaxf(b, -z[i][s]);
        }
    }
#pragma unroll
    for (int o = 16; o; o >>= 1) {
        a = fmaxf(a, __shfl_xor_sync(0xffffffffu, a, o));
        b = fmaxf(b, __shfl_xor_sync(0xffffffffu, b, o));
    }
    float sa = 0.f, sb = 0.f;
#pragma unroll
    for (int i = 0; i < 8; i++) {
        int ty[4] = {t4[i].x, t4[i].y, t4[i].z, t4[i].w};
#pragma unroll
        for (int s = 0; s < 4; s++) {
            if (ty[s] == 3) sa += __expf(z[i][s] - a);
            if (ty[s] == 4) sb += __expf(-z[i][s] - b);
        }
    }
#pragma unroll
    for (int o = 16; o; o >>= 1) {
        sa += __shfl_xor_sync(0xffffffffu, sa, o);
        sb += __shfl_xor_sync(0xffffffffu, sb, o);
    }
    float inv3 = __frcp_rn(sa), inv4 = __frcp_rn(sb);

    float acc[10];
#pragma unroll
    for (int j = 0; j < 10; j++) acc[j] = 0.f;

#pragma unroll
    for (int i = 0; i < 8; i++) {
        int ty[4] = {t4[i].x, t4[i].y, t4[i].z, t4[i].w};
        float mk[4] = {m4[i].x, m4[i].y, m4[i].z, m4[i].w};
        float r0 = act_eval(z[i][0], ty[0], a, inv3, b, inv4) * mk[0] * 2.0f;
        float r1 = act_eval(z[i][1], ty[1], a, inv3, b, inv4) * mk[1] * 2.0f;
        float r2 = act_eval(z[i][2], ty[2], a, inv3, b, inv4) * mk[2] * 2.0f;
        float r3 = act_eval(z[i][3], ty[3], a, inv3, b, inv4) * mk[3] * 2.0f;
        int colbase = lane * 4 + i * 128;
#pragma unroll
        for (int j = 0; j < 10; j++) {
            float4 w = *(const float4*)(W3 + (size_t)j * HDIM + colbase);
            acc[j] += r0 * w.x + r1 * w.y + r2 * w.z + r3 * w.w;
        }
    }
#pragma unroll
    for (int j = 0; j < 10; j++)
#pragma unroll
        for (int o = 16; o; o >>= 1)
            acc[j] += __shfl_xor_sync(0xffffffffu, acc[j], o);

    float logits[10];
    float m = -1e30f;
#pragma unroll
    for (int j = 0; j < 10; j++) {
        logits[j] = acc[j] + __ldg(b3 + j);
        m = fmaxf(m, logits[j]);
    }
    float s = 0.f;
#pragma unroll
    for (int j = 0; j < 10; j++) s += __expf(logits[j] - m);
    float lse = m + logf(s);
    if (lane == 0) {
#pragma unroll
        for (int j = 0; j < 10; j++) out[row * 10 + j] = logits[j] - lse;
    }
}

// ---------------------------------------------------------------------------
// Launch
// ---------------------------------------------------------------------------
extern "C" void kernel_launch(void* const* d_in, const int* in_sizes, int n_in,
                              void* d_out, int out_size) {
    const float* x     = (const float*)d_in[0];
    const float* W0    = (const float*)d_in[1];
    const float* b0    = (const float*)d_in[2];
    const float* W1    = (const float*)d_in[3];
    const float* b1    = (const float*)d_in[4];
    const float* W2    = (const float*)d_in[5];
    const float* b2    = (const float*)d_in[6];
    const float* W3    = (const float*)d_in[7];
    const float* b3    = (const float*)d_in[8];
    const float* mask1 = (const float*)d_in[9];
    const float* mask2 = (const float*)d_in[10];
    const float* mask3 = (const float*)d_in[11];
    const int* type_ids = (const int*)d_in[12];

    __half* zbuf = nullptr;
    __half* hbuf = nullptr;
    __half* xh   = nullptr;
    __half* w0h  = nullptr;
    __half* w1h  = nullptr;
    __half* w2h  = nullptr;
    cudaGetSymbolAddress((void**)&zbuf, g_z);
    cudaGetSymbolAddress((void**)&hbuf, g_h);
    cudaGetSymbolAddress((void**)&xh, g_xh);
    cudaGetSymbolAddress((void**)&w0h, g_w0h);
    cudaGetSymbolAddress((void**)&w1h, g_w1h);
    cudaGetSymbolAddress((void**)&w2h, g_w2h);
    float* out = (float*)d_out;

    const int smemBytes = GSTAGES * STG_BYTES + 1024;
    cudaFuncSetAttribute(gemm_fp16_kernel,
                         cudaFuncAttributeMaxDynamicSharedMemorySize, smemBytes);

    // fp32 -> fp16 conversions
    f2h_kernel<<<1024, 256>>>(x, xh, (int)((size_t)BATCH * DIN / 4));
    f2h_kernel<<<256, 256>>>(W0, w0h, HDIM * DIN / 4);
    f2h_kernel<<<256, 256>>>(W1, w1h, HDIM * HDIM / 4);
    f2h_kernel<<<256, 256>>>(W2, w2h, HDIM * HDIM / 4);

    const size_t maskElems = (size_t)BATCH * HDIM;
    float* mdst = out + (size_t)BATCH * 10;

    dim3 gg(HDIM / 128, BATCH / 128);
    gemm_fp16_kernel<<<gg, 256, smemBytes>>>(xh, w0h, b0, zbuf, DIN);
    act_kernel<<<BATCH / 4, 128>>>(zbuf, type_ids, mask1, mdst, hbuf);
    gemm_fp16_kernel<<<gg, 256, smemBytes>>>(hbuf, w1h, b1, zbuf, HDIM);
    act_kernel<<<BATCH / 4, 128>>>(zbuf, type_ids + HDIM, mask2, mdst + maskElems,
                                   hbuf);
    gemm_fp16_kernel<<<gg, 256, smemBytes>>>(hbuf, w2h, b2, zbuf, HDIM);
    act3_head_kernel<<<BATCH / 4, 128>>>(zbuf, type_ids + 2 * HDIM, mask3,
                                         mdst + 2 * maskElems, W3, b3, out);
}